// round 13
// baseline (speedup 1.0000x reference)
#include <cuda_runtime.h>

// EPLoss edit-probability DP, anti-diagonal wavefront, one warp per batch item.
// B=128, n_y=512, n_T=128, C=128. EOS label = 1.
//
// R13: R12 still ran at CPI~2.7 because every step carried asm volatile
// cp.async/commit statements, which NVCC schedules around conservatively ->
// the 8-step unrolled block behaved as 8 scheduling islands and the per-step
// LDS(29)/shfl(26) latencies stayed exposed. Now staging is batched per
// 8-column GROUP at the head of each block (16 cp.async + 1 commit), with
// wait_group 3 covering a 3-group (24-column) pipeline. The 8-step body is
// pure C — no asm — so ptxas can hoist all 64 gathers across the block.

#define NY 512
#define NT 128
#define CC 128
#define RING 64          // ring slots (power of 2)
#define PADW 132         // 128 data + 4 pad floats (pad[0] == 0 used by lane 0)
#define PADB (PADW * 4)

__global__ __launch_bounds__(32, 1)
void ep_wavefront(const float* __restrict__ pred,
                  const float* __restrict__ R,
                  const float* __restrict__ Iins,
                  const int* __restrict__ target,
                  float* __restrict__ out) {
    extern __shared__ float smem[];
    float*  ringP = smem;                                // [RING][PADW]: pred[b, c-1, :]
    float*  ringI = smem + RING * PADW;                  // [RING][PADW]: I[b, c, :]
    float4* Rs    = (float4*)(smem + 2 * RING * PADW);   // [NY]: {R0, Rins, R2, 0}

    const int b    = blockIdx.x;
    const int lane = threadIdx.x;

    const float* __restrict__ predb = pred + (size_t)b * NY * CC;
    const float* __restrict__ Ib    = Iins + (size_t)b * NY * CC;
    const float* __restrict__ Rb    = R    + (size_t)b * NY * 3;
    const int*   __restrict__ tb    = target + b * NT;

    const unsigned ringPs = (unsigned)__cvta_generic_to_shared(ringP);
    const unsigned ringIs = (unsigned)__cvta_generic_to_shared(ringI);
    const unsigned laneOff = (unsigned)(lane * 16);
    const float* __restrict__ srcPb = predb + lane * 4;
    const float* __restrict__ srcIb = Ib + lane * 4;

    // Zero the pad words of every ring row (lane 0 gathers from pad -> 0).
    for (int k = lane; k < RING * 4; k += 32) {
        const int slot = k >> 2, w = k & 3;
        ringP[slot * PADW + CC + w] = 0.0f;
        ringI[slot * PADW + CC + w] = 0.0f;
    }

    // Stage column group K_: columns 8K_+1 .. 8K_+8 (source clamped to 511;
    // slot uses the UNclamped index). One commit group per call.
#define STAGE_GROUP(K_) do {                                                    \
    _Pragma("unroll")                                                           \
    for (int q_ = 1; q_ <= 8; ++q_) {                                           \
        const int cs_ = 8 * (K_) + q_;                                          \
        const int c_  = (cs_ < NY - 1) ? cs_ : (NY - 1);                        \
        const unsigned so_ = (unsigned)(cs_ & (RING - 1)) * PADB + laneOff;     \
        const float* sP_ = srcPb + (c_ - 1) * CC;                               \
        const float* sI_ = srcIb + c_ * CC;                                     \
        asm volatile("cp.async.cg.shared.global [%0], [%1], 16;"                \
                     :: "r"(ringPs + so_), "l"(sP_));                           \
        asm volatile("cp.async.cg.shared.global [%0], [%1], 16;"                \
                     :: "r"(ringIs + so_), "l"(sI_));                           \
    }                                                                           \
    asm volatile("cp.async.commit_group;");                                     \
} while (0)

    // Prologue: groups 0..2 (columns 1..24).
    STAGE_GROUP(0); STAGE_GROUP(1); STAGE_GROUP(2);

    // Pack R into shared as float4 rows.
    for (int j = lane; j < NY; j += 32) {
        const float r0 = Rb[3 * j + 0];
        const float r1 = Rb[3 * j + 1];
        const float r2 = Rb[3 * j + 2];
        Rs[j] = make_float4(r0, (j == NY - 1) ? 1.0f : r1, r2, 0.0f);
    }

    const int r0row = lane * 4;
    const int tt0 = tb[r0row + 0];
    const int tt1 = tb[r0row + 1];
    const int tt2 = tb[r0row + 2];
    const int tt3 = tb[r0row + 3];
    // Gather indices: tg0 is t_{row-1}; lane 0 points at the zero pad word.
    const int tg0 = lane ? tb[r0row - 1] : CC;
    const int tg1 = tt0, tg2 = tt1, tg3 = tt2;
    const bool e0 = (tt0 == 1), e1 = (tt1 == 1), e2 = (tt2 == 1), e3 = (tt3 == 1);
    const bool isl0 = (lane == 0);

    // Column-0 coefficients hoisted: pI(i-1, 1) = Rins[1]*I[b,1,t_{i-1}]
    const float rins1 = Rb[3 * 1 + 1];
    const float pI1_0 = rins1 * Ib[CC + (lane ? tb[r0row - 1] : 0)];  // unused on lane 0
    const float pI1_1 = rins1 * Ib[CC + tg1];
    const float pI1_2 = rins1 * Ib[CC + tg2];
    const float pI1_3 = rins1 * Ib[CC + tg3];

    __syncwarp();  // pads + Rs visible

    float cur0 = 0.f, cur1 = 0.f, cur2 = 0.f, cur3 = 0.f;
    float carry = 0.f;   // cur3 at end of previous step
    float upp   = 0.f;   // previous step's shfl result = ep[r0-1, j-1]
    float rpx   = 0.f;   // R0[j-1]
    float rpz   = 0.f;   // R2[j-1]

    // Unified j>=1 body. Lane 0: g0=h0=0 (pad word) -> n0 = cur0 * pd0 with
    // pd0 = e0 ? 1 : R2[j]  == row-0 cumprod. Chain: n_k = fmaf(n_{k-1}, rh_k, c_k).
#define BODY(J_, UPC_) do {                                                     \
    const int slotc_ = (J_) & (RING - 1);                                       \
    const float* __restrict__ bP_ = ringP + slotc_ * PADW;                      \
    const float* __restrict__ bI_ = ringI + slotc_ * PADW;                      \
    const float g0_ = bP_[tg0], g1_ = bP_[tg1], g2_ = bP_[tg2], g3_ = bP_[tg3]; \
    const float h0_ = bI_[tg0], h1_ = bI_[tg1], h2_ = bI_[tg2], h3_ = bI_[tg3]; \
    const float4 rj_ = Rs[(J_)];                                                \
    const float rins_ = rj_.y;                                                  \
    const float pz0_ = isl0 ? rj_.z : rpz;                                      \
    const float pd0_ = e0 ? 1.0f : pz0_;                                        \
    const float pd1_ = e1 ? 1.0f : rpz;                                         \
    const float pd2_ = e2 ? 1.0f : rpz;                                         \
    const float pd3_ = e3 ? 1.0f : rpz;                                         \
    const float rg0_ = rpx * g0_, rg1_ = rpx * g1_;                             \
    const float rg2_ = rpx * g2_, rg3_ = rpx * g3_;                             \
    const float rh0_ = rins_ * h0_, rh1_ = rins_ * h1_;                         \
    const float rh2_ = rins_ * h2_, rh3_ = rins_ * h3_;                         \
    const float c0_ = fmaf(upp,  rg0_, cur0 * pd0_);                            \
    const float n0_ = fmaf((UPC_), rh0_, c0_);                                  \
    const float c1_ = fmaf(cur0, rg1_, cur1 * pd1_);                            \
    const float n1_ = fmaf(n0_, rh1_, c1_);                                     \
    const float c2_ = fmaf(cur1, rg2_, cur2 * pd2_);                            \
    const float n2_ = fmaf(n1_, rh2_, c2_);                                     \
    const float c3_ = fmaf(cur2, rg3_, cur3 * pd3_);                            \
    const float n3_ = fmaf(n2_, rh3_, c3_);                                     \
    cur0 = n0_; cur1 = n1_; cur2 = n2_; cur3 = n3_;                             \
    rpx = rj_.x; rpz = rj_.z;                                                   \
} while (0)

#define RAMP_STEP(S_) do {                                                      \
    const float upc_ = __shfl_up_sync(0xffffffffu, carry, 1);                   \
    const int j_ = (S_) - lane;                                                 \
    if (j_ >= 0) {                                                              \
        if (j_ == 0) {                                                          \
            cur0 = lane ? (upc_ * pI1_0) : 1.0f;                                \
            cur1 = cur0 * pI1_1;                                                \
            cur2 = cur1 * pI1_2;                                                \
            cur3 = cur2 * pI1_3;                                                \
            const float4 r0_ = Rs[0];                                           \
            rpx = r0_.x; rpz = r0_.z;                                           \
        } else {                                                                \
            BODY(j_, upc_);                                                     \
        }                                                                       \
    }                                                                           \
    upp = upc_; carry = cur3;                                                   \
} while (0)

#define STEADY_STEP(S_) do {                                                    \
    const float upc_ = __shfl_up_sync(0xffffffffu, carry, 1);                   \
    BODY((S_) - lane, upc_);                                                    \
    upp = upc_; carry = cur3;                                                   \
} while (0)

#define EPI_STEP(S_) do {                                                       \
    const float upc_ = __shfl_up_sync(0xffffffffu, carry, 1);                   \
    const int j_ = (S_) - lane;                                                 \
    if (j_ < NY) { BODY(j_, upc_); }                                            \
    upp = upc_; carry = cur3;                                                   \
} while (0)

#define FENCE3() do {                                                           \
    asm volatile("cp.async.wait_group 3;" ::: "memory");                        \
    __syncwarp();                                                               \
} while (0)

    // Ramp-up: blocks i = 0..3 (s in [0, 32)). j = s-lane may be <0 or 0.
    for (int i = 0; i < 4; ++i) {
        const int sb = 8 * i;
        STAGE_GROUP(i + 3);
        FENCE3();
        RAMP_STEP(sb + 0); RAMP_STEP(sb + 1); RAMP_STEP(sb + 2); RAMP_STEP(sb + 3);
        RAMP_STEP(sb + 4); RAMP_STEP(sb + 5); RAMP_STEP(sb + 6); RAMP_STEP(sb + 7);
    }

    // Steady: blocks i = 4..63 (s in [32, 512)). Body is pure C — no asm.
    for (int i = 4; i < 64; ++i) {
        const int sb = 8 * i;
        STAGE_GROUP(i + 3);
        FENCE3();
        STEADY_STEP(sb + 0); STEADY_STEP(sb + 1); STEADY_STEP(sb + 2); STEADY_STEP(sb + 3);
        STEADY_STEP(sb + 4); STEADY_STEP(sb + 5); STEADY_STEP(sb + 6); STEADY_STEP(sb + 7);
    }

    // Epilogue: s in [512, 544). All columns already staged.
    asm volatile("cp.async.wait_group 0;" ::: "memory");
    __syncwarp();
    for (int s = NY; s < NY + 32; ++s) {
        EPI_STEP(s);
    }

    if (lane == 31) out[b] = cur3;
}

static const int kSmemBytes = 2 * RING * PADW * 4 + NY * 16;  // 75,776 B

extern "C" void kernel_launch(void* const* d_in, const int* in_sizes, int n_in,
                              void* d_out, int out_size) {
    const float* pred   = (const float*)d_in[0];
    const float* R      = (const float*)d_in[1];
    const float* Iins   = (const float*)d_in[2];
    const int*   target = (const int*)d_in[3];
    float* out = (float*)d_out;

    cudaFuncSetAttribute(ep_wavefront,
                         cudaFuncAttributeMaxDynamicSharedMemorySize, kSmemBytes);

    const int B = out_size;  // 128
    ep_wavefront<<<B, 32, kSmemBytes>>>(pred, R, Iins, target, out);
}